// round 2
// baseline (speedup 1.0000x reference)
#include <cuda_runtime.h>
#include <stdint.h>

#define BB 2
#define HH 16
#define SS 2048
#define DD 128
#define BM 64
#define BN 64
#define SQS 132   // padded row stride for Q/K tiles (floats)
#define SPS 68    // padded row stride for P tile (floats)
#define NT 256

// threefry-2x32 with key = (0, 42)  == jax.random.key(42) key data
// Verified against Random123 KAT: key=(0,0), ctr=(0,0) -> (0x6b200159, 0x99ba4efe)
static __device__ __forceinline__ uint2 tf2x32_42(uint32_t x0, uint32_t x1) {
    const uint32_t K0 = 0u;
    const uint32_t K1 = 42u;
    const uint32_t K2 = 0x1BD11BDAu ^ 0u ^ 42u;
    x0 += K0; x1 += K1;
#define TFR(R) { x0 += x1; x1 = __funnelshift_l(x1, x1, (R)); x1 ^= x0; }
    TFR(13) TFR(15) TFR(26) TFR(6)
    x0 += K1; x1 += K2 + 1u;
    TFR(17) TFR(29) TFR(16) TFR(24)
    x0 += K2; x1 += K0 + 2u;
    TFR(13) TFR(15) TFR(26) TFR(6)
    x0 += K0; x1 += K1 + 3u;
    TFR(17) TFR(29) TFR(16) TFR(24)
    x0 += K1; x1 += K2 + 4u;
    TFR(13) TFR(15) TFR(26) TFR(6)
    x0 += K2; x1 += K0 + 5u;
#undef TFR
    return make_uint2(x0, x1);
}

// jax_threefry_partitionable=True semantics (JAX >= 0.4.30 default):
// word(i) = hi ^ lo of threefry2x32(key, (i>>32, i&0xffffffff)); keep iff MSB==0.
static __device__ __forceinline__ uint32_t tf_word(uint32_t idx) {
    uint2 r = tf2x32_42(0u, idx);
    return r.x ^ r.y;
}

__global__ __launch_bounds__(NT, 2)
void attn_dropout_kernel(const float* __restrict__ Qg,
                         const float* __restrict__ Kg,
                         const float* __restrict__ Vg,
                         float* __restrict__ Og) {
    extern __shared__ float smem[];
    float* sQ = smem;                   // BM x SQS
    float* sK = smem + BM * SQS;        // BN x SQS   (aliased as P tile, BM x SPS)
    float* sV = smem + 2 * BM * SQS;    // BN x DD
    float* sP = sK;

    const int tid = threadIdx.x;
    const int tx = tid & 15;            // 0..15
    const int ty = tid >> 4;            // 0..15
    const int bh = blockIdx.y;          // b*16 + h
    const int q0 = blockIdx.x * BM;

    const float* Qp = Qg + ((size_t)bh * SS + q0) * DD;
    const float* Kp = Kg + (size_t)bh * SS * DD;
    const float* Vp = Vg + (size_t)bh * SS * DD;

    // ---- Load Q tile [64 x 128] ----
    #pragma unroll
    for (int it = 0; it < (BM * DD) / (4 * NT); it++) {
        int e = (tid + it * NT) * 4;
        int r = e >> 7, c = e & 127;
        *(float4*)(sQ + r * SQS + c) = *(const float4*)(Qp + e);
    }

    float acc[4][8];
    #pragma unroll
    for (int j = 0; j < 4; j++)
        #pragma unroll
        for (int i = 0; i < 8; i++) acc[j][i] = 0.f;
    float dsum[4] = {0.f, 0.f, 0.f, 0.f};

    const float scale = 0.08838834764831845f;  // 1/sqrt(128)

    for (int kb = 0; kb < SS / BN; kb++) {
        __syncthreads();   // previous iteration done with sP(=sK)/sV
        const float* Kb = Kp + (size_t)kb * BN * DD;
        const float* Vb = Vp + (size_t)kb * BN * DD;
        #pragma unroll
        for (int it = 0; it < (BN * DD) / (4 * NT); it++) {
            int e = (tid + it * NT) * 4;
            int r = e >> 7, c = e & 127;
            *(float4*)(sK + r * SQS + c) = *(const float4*)(Kb + e);
            *(float4*)(sV + r * DD  + c) = *(const float4*)(Vb + e);
        }
        __syncthreads();

        // ---- S tile: [64 x 64] = Q K^T, 4x4 micro-tile per thread ----
        float sacc[4][4];
        #pragma unroll
        for (int j = 0; j < 4; j++)
            #pragma unroll
            for (int i = 0; i < 4; i++) sacc[j][i] = 0.f;

        #pragma unroll 4
        for (int d0 = 0; d0 < DD; d0 += 4) {
            float4 aq[4], bk[4];
            #pragma unroll
            for (int j = 0; j < 4; j++)
                aq[j] = *(const float4*)(sQ + (4 * ty + j) * SQS + d0);
            #pragma unroll
            for (int i = 0; i < 4; i++)
                bk[i] = *(const float4*)(sK + (tx + 16 * i) * SQS + d0);
            #pragma unroll
            for (int j = 0; j < 4; j++)
                #pragma unroll
                for (int i = 0; i < 4; i++)
                    sacc[j][i] += aq[j].x * bk[i].x + aq[j].y * bk[i].y
                                + aq[j].z * bk[i].z + aq[j].w * bk[i].w;
        }
        __syncthreads();   // everyone done reading sK before P overwrites it

        // ---- exp + threefry dropout mask (partitionable), write P ----
        // flat index = bh<<22 | q<<11 | k  (bh = b*16+h, so this is b<<26|h<<22|q<<11|k)
        uint32_t baseIdx = ((uint32_t)bh << 22) | ((uint32_t)q0 << 11)
                         | (uint32_t)(kb * BN);
        #pragma unroll
        for (int j = 0; j < 4; j++) {
            #pragma unroll
            for (int i = 0; i < 4; i++) {
                float ex = __expf(sacc[j][i] * scale);
                dsum[j] += ex;   // denominator uses UNmasked sum
                uint32_t idx = baseIdx + ((uint32_t)(4 * ty + j) << 11)
                             + (uint32_t)(tx + 16 * i);
                uint32_t w = tf_word(idx);
                // keep iff uniform<0.5 iff MSB==0
                sP[(4 * ty + j) * SPS + (tx + 16 * i)] = (w & 0x80000000u) ? 0.f : ex;
            }
        }
        __syncthreads();

        // ---- O += P V : 4x8 micro-tile per thread ----
        #pragma unroll 2
        for (int c0 = 0; c0 < BN; c0 += 4) {
            float4 p4[4];
            #pragma unroll
            for (int j = 0; j < 4; j++)
                p4[j] = *(const float4*)(sP + (4 * ty + j) * SPS + c0);
            #pragma unroll
            for (int cc = 0; cc < 4; cc++) {
                float bb[8];
                #pragma unroll
                for (int i = 0; i < 8; i++)
                    bb[i] = sV[(c0 + cc) * DD + tx + 16 * i];
                #pragma unroll
                for (int j = 0; j < 4; j++) {
                    float pj = ((const float*)&p4[j])[cc];
                    #pragma unroll
                    for (int i = 0; i < 8; i++)
                        acc[j][i] += pj * bb[i];
                }
            }
        }
    }

    // ---- reduce row denominators across the 16 tx threads ----
    __syncthreads();
    #pragma unroll
    for (int j = 0; j < 4; j++)
        sP[(4 * ty + j) * SPS + tx] = dsum[j];
    __syncthreads();

    #pragma unroll
    for (int j = 0; j < 4; j++) {
        float s = 0.f;
        #pragma unroll
        for (int t = 0; t < 16; t++) s += sP[(4 * ty + j) * SPS + t];
        float rs = 2.0f / s;   // fold dropout 1/(1-p)=2 into normalization
        size_t orow = ((size_t)bh * SS + (size_t)(q0 + 4 * ty + j)) * DD;
        #pragma unroll
        for (int i = 0; i < 8; i++)
            Og[orow + tx + 16 * i] = acc[j][i] * rs;
    }
}

#define SMEM_BYTES ((2 * BM * SQS + BN * DD) * 4)   // 100352 B

extern "C" void kernel_launch(void* const* d_in, const int* in_sizes, int n_in,
                              void* d_out, int out_size) {
    (void)in_sizes; (void)n_in; (void)out_size;
    const float* Q = (const float*)d_in[0];
    const float* K = (const float*)d_in[1];
    const float* V = (const float*)d_in[2];
    float* O = (float*)d_out;

    cudaFuncSetAttribute(attn_dropout_kernel,
                         cudaFuncAttributeMaxDynamicSharedMemorySize, SMEM_BYTES);
    dim3 grid(SS / BM, BB * HH);
    attn_dropout_kernel<<<grid, NT, SMEM_BYTES>>>(Q, K, V, O);
}

// round 4
// speedup vs baseline: 2.3768x; 2.3768x over previous
#include <cuda_runtime.h>
#include <stdint.h>

#define SS 2048
#define DDIM 128
#define NT 256

// ===========================================================================
// threefry-2x32, key=(0,42); jax_threefry_partitionable semantics:
// word(i) = hi ^ lo of threefry2x32(key, ctr=(0, i)); keep iff MSB==0.
// ===========================================================================
static __device__ __forceinline__ uint32_t tf_word(uint32_t idx) {
    const uint32_t K0 = 0u, K1 = 42u, K2 = 0x1BD11BDAu ^ 42u;
    uint32_t x0 = 0u + K0, x1 = idx + K1;
#define TFR(R) { x0 += x1; x1 = __funnelshift_l(x1, x1, (R)); x1 ^= x0; }
    TFR(13) TFR(15) TFR(26) TFR(6)
    x0 += K1; x1 += K2 + 1u;
    TFR(17) TFR(29) TFR(16) TFR(24)
    x0 += K2; x1 += K0 + 2u;
    TFR(13) TFR(15) TFR(26) TFR(6)
    x0 += K0; x1 += K1 + 3u;
    TFR(17) TFR(29) TFR(16) TFR(24)
    x0 += K1; x1 += K2 + 4u;
    TFR(13) TFR(15) TFR(26) TFR(6)
    x0 += K2; x1 += K0 + 5u;
#undef TFR
    return x0 ^ x1;
}

// ===========================================================================
// Fallback SIMT kernel (the R2 kernel that passed at 2073 us)
// ===========================================================================
#define FBM 64
#define FBN 64
#define SQS 132
#define SPS 68

__global__ __launch_bounds__(NT, 2)
void attn_dropout_kernel(const float* __restrict__ Qg,
                         const float* __restrict__ Kg,
                         const float* __restrict__ Vg,
                         float* __restrict__ Og) {
    extern __shared__ float fsm[];
    float* sQ = fsm;
    float* sK = fsm + FBM * SQS;
    float* sV = fsm + 2 * FBM * SQS;
    float* sP = sK;

    const int tid = threadIdx.x;
    const int tx = tid & 15;
    const int ty = tid >> 4;
    const int bh = blockIdx.y;
    const int q0 = blockIdx.x * FBM;

    const float* Qp = Qg + ((size_t)bh * SS + q0) * DDIM;
    const float* Kp = Kg + (size_t)bh * SS * DDIM;
    const float* Vp = Vg + (size_t)bh * SS * DDIM;

    #pragma unroll
    for (int it = 0; it < (FBM * DDIM) / (4 * NT); it++) {
        int e = (tid + it * NT) * 4;
        int r = e >> 7, c = e & 127;
        *(float4*)(sQ + r * SQS + c) = *(const float4*)(Qp + e);
    }

    float acc[4][8];
    #pragma unroll
    for (int j = 0; j < 4; j++)
        #pragma unroll
        for (int i = 0; i < 8; i++) acc[j][i] = 0.f;
    float dsum[4] = {0.f, 0.f, 0.f, 0.f};

    const float scale = 0.08838834764831845f;

    for (int kb = 0; kb < SS / FBN; kb++) {
        __syncthreads();
        const float* Kb = Kp + (size_t)kb * FBN * DDIM;
        const float* Vb = Vp + (size_t)kb * FBN * DDIM;
        #pragma unroll
        for (int it = 0; it < (FBN * DDIM) / (4 * NT); it++) {
            int e = (tid + it * NT) * 4;
            int r = e >> 7, c = e & 127;
            *(float4*)(sK + r * SQS + c) = *(const float4*)(Kb + e);
            *(float4*)(sV + r * DDIM + c) = *(const float4*)(Vb + e);
        }
        __syncthreads();

        float sacc[4][4];
        #pragma unroll
        for (int j = 0; j < 4; j++)
            #pragma unroll
            for (int i = 0; i < 4; i++) sacc[j][i] = 0.f;

        #pragma unroll 4
        for (int d0 = 0; d0 < DDIM; d0 += 4) {
            float4 aq[4], bk[4];
            #pragma unroll
            for (int j = 0; j < 4; j++)
                aq[j] = *(const float4*)(sQ + (4 * ty + j) * SQS + d0);
            #pragma unroll
            for (int i = 0; i < 4; i++)
                bk[i] = *(const float4*)(sK + (tx + 16 * i) * SQS + d0);
            #pragma unroll
            for (int j = 0; j < 4; j++)
                #pragma unroll
                for (int i = 0; i < 4; i++)
                    sacc[j][i] += aq[j].x * bk[i].x + aq[j].y * bk[i].y
                                + aq[j].z * bk[i].z + aq[j].w * bk[i].w;
        }
        __syncthreads();

        uint32_t baseIdx = ((uint32_t)bh << 22) | ((uint32_t)q0 << 11)
                         | (uint32_t)(kb * FBN);
        #pragma unroll
        for (int j = 0; j < 4; j++) {
            #pragma unroll
            for (int i = 0; i < 4; i++) {
                float ex = __expf(sacc[j][i] * scale);
                dsum[j] += ex;
                uint32_t idx = baseIdx + ((uint32_t)(4 * ty + j) << 11)
                             + (uint32_t)(tx + 16 * i);
                uint32_t w = tf_word(idx);
                sP[(4 * ty + j) * SPS + (tx + 16 * i)] = (w & 0x80000000u) ? 0.f : ex;
            }
        }
        __syncthreads();

        #pragma unroll 2
        for (int c0 = 0; c0 < FBN; c0 += 4) {
            float4 p4[4];
            #pragma unroll
            for (int j = 0; j < 4; j++)
                p4[j] = *(const float4*)(sP + (4 * ty + j) * SPS + c0);
            #pragma unroll
            for (int cc = 0; cc < 4; cc++) {
                float bb[8];
                #pragma unroll
                for (int i = 0; i < 8; i++)
                    bb[i] = sV[(c0 + cc) * DDIM + tx + 16 * i];
                #pragma unroll
                for (int j = 0; j < 4; j++) {
                    float pj = ((const float*)&p4[j])[cc];
                    #pragma unroll
                    for (int i = 0; i < 8; i++)
                        acc[j][i] += pj * bb[i];
                }
            }
        }
    }

    __syncthreads();
    #pragma unroll
    for (int j = 0; j < 4; j++)
        sP[(4 * ty + j) * SPS + tx] = dsum[j];
    __syncthreads();

    #pragma unroll
    for (int j = 0; j < 4; j++) {
        float s = 0.f;
        #pragma unroll
        for (int t = 0; t < 16; t++) s += sP[(4 * ty + j) * SPS + t];
        float rs = 2.0f / s;
        size_t orow = ((size_t)bh * SS + (size_t)(q0 + 4 * ty + j)) * DDIM;
        #pragma unroll
        for (int i = 0; i < 8; i++)
            Og[orow + tx + 16 * i] = acc[j][i] * rs;
    }
}

#define FB_SMEM ((2 * FBM * SQS + FBN * DDIM) * 4)

// ===========================================================================
// tcgen05 kernel — only compiled on the sm_103a (arch-specific) pass.
// ===========================================================================
#if !defined(__CUDA_ARCH__) || defined(__CUDA_ARCH_FEAT_SM103_ALL) || \
    (defined(__CUDA_ARCH_SPECIFIC__) && (__CUDA_ARCH_SPECIFIC__ >= 1000))
#define TC_PATH_COMPILED 1
#else
#define TC_PATH_COMPILED 0
#endif
// Device-code availability (host pass must still see a definition, but it
// contains no tcgen05 asm unless the device pass supports it).
#if defined(__CUDA_ARCH__) && TC_PATH_COMPILED
#define TC_DEV 1
#else
#define TC_DEV 0
#endif

#define BM 128
#define BN 64
#define NKB (SS / BN)

#define T_QHI 0
#define T_QLO 64
#define T_S   128
#define T_PHI 192
#define T_PLO 224
#define T_O   256
#define TMEM_COLS 512

#define SM_BUFSZ 65536
#define SM_KHI 0
#define SM_KLO 16384
#define SM_VHI 32768
#define SM_VLO 49152
#define SM_DSUM 131072
#define SM_TPTR 132096
#define SM_MB1  132104
#define SM_MB2  132112
#define TC_SMEM 132160

#define IDESC_N64  0x8100490u
#define IDESC_N128 0x8200490u

static __device__ __forceinline__ uint32_t smem_u32(const void* p) {
    uint32_t a;
    asm("{ .reg .u64 t; cvta.to.shared.u64 t, %1; cvt.u32.u64 %0, t; }" : "=r"(a) : "l"(p));
    return a;
}
static __device__ __forceinline__ uint32_t swz(uint32_t o) { return o ^ ((o >> 3) & 0x70u); }
static __device__ __forceinline__ uint32_t koff(int n, int k, int nrows) {
    return ((uint32_t)((n >> 3) + ((k >> 6) * (nrows >> 3))) << 10)
         + (((uint32_t)n & 7u) << 7) + (((uint32_t)k & 63u) << 1);
}
static __device__ __forceinline__ uint32_t prmt_hi(uint32_t a, uint32_t b) {
    uint32_t r; asm("prmt.b32 %0,%1,%2,0x7632;" : "=r"(r) : "r"(a), "r"(b)); return r;
}
static __device__ __forceinline__ float trunc_bf(float x) {
    return __uint_as_float(__float_as_uint(x) & 0xffff0000u);
}
static __device__ __forceinline__ uint32_t pack_bf2(float hi_elem, float lo_elem) {
    uint32_t r; asm("cvt.rn.bf16x2.f32 %0,%1,%2;" : "=r"(r) : "f"(hi_elem), "f"(lo_elem)); return r;
}

static constexpr uint64_t DESC_BASE =
    (uint64_t(2) << 61) | (uint64_t(1) << 46) | (uint64_t(64) << 32) | (uint64_t(1) << 16);
static __device__ __forceinline__ uint64_t mk_desc(uint32_t addr) {
    return DESC_BASE | ((uint64_t)(addr >> 4) & 0x3FFFull);
}

#if TC_DEV
static __device__ __forceinline__ void mma_f16(uint32_t d, uint32_t a, uint64_t bdesc,
                                               uint32_t idesc, int acc) {
    asm volatile(
        "{\n\t.reg .pred p;\n\tsetp.ne.u32 p,%5,0;\n\t"
        "tcgen05.mma.cta_group::1.kind::f16 [%0],[%1],%2,%3,{%4,%4,%4,%4},p;\n\t}"
        :: "r"(d), "r"(a), "l"(bdesc), "r"(idesc), "r"(0u), "r"((uint32_t)acc) : "memory");
}

#define TMEM_ALLOC(sa, n)  asm volatile("tcgen05.alloc.cta_group::1.sync.aligned.shared::cta.b32 [%0], %1;" :: "r"(sa), "r"((uint32_t)(n)) : "memory")
#define TMEM_DEALLOC(t, n) asm volatile("tcgen05.dealloc.cta_group::1.sync.aligned.b32 %0, %1;" :: "r"(t), "r"((uint32_t)(n)))
#define TMEM_RELINQ()      asm volatile("tcgen05.relinquish_alloc_permit.cta_group::1.sync.aligned;")
#define TC_COMMIT(mb)      asm volatile("tcgen05.commit.cta_group::1.mbarrier::arrive::one.shared::cluster.b64 [%0];" :: "r"(mb) : "memory")
#define TC_WAIT_LD()       asm volatile("tcgen05.wait::ld.sync.aligned;" ::: "memory")
#define TC_WAIT_ST()       asm volatile("tcgen05.wait::st.sync.aligned;" ::: "memory")
#define TC_FENCE_BEFORE()  asm volatile("tcgen05.fence::before_thread_sync;" ::: "memory")
#define TC_FENCE_AFTER()   asm volatile("tcgen05.fence::after_thread_sync;" ::: "memory")
#define MBAR_INIT(mb, c)   asm volatile("mbarrier.init.shared.b64 [%0], %1;" :: "r"(mb), "r"((uint32_t)(c)) : "memory")

static __device__ __forceinline__ void mbar_wait(uint32_t mb, uint32_t parity) {
    asm volatile(
        "{\n\t.reg .pred P;\n\t"
        "W%=:\n\tmbarrier.try_wait.parity.acquire.cta.shared::cta.b64 P, [%0], %1, 0x989680;\n\t"
        "@P bra.uni D%=;\n\tbra.uni W%=;\n\tD%=:\n\t}"
        :: "r"(mb), "r"(parity) : "memory");
}

#define LDTM_X32(r, a) \
    asm volatile("tcgen05.ld.sync.aligned.32x32b.x32.b32 " \
        "{%0,%1,%2,%3,%4,%5,%6,%7,%8,%9,%10,%11,%12,%13,%14,%15," \
        "%16,%17,%18,%19,%20,%21,%22,%23,%24,%25,%26,%27,%28,%29,%30,%31}, [%32];" \
        : "=r"((r)[0]),"=r"((r)[1]),"=r"((r)[2]),"=r"((r)[3]),"=r"((r)[4]),"=r"((r)[5]),"=r"((r)[6]),"=r"((r)[7]), \
          "=r"((r)[8]),"=r"((r)[9]),"=r"((r)[10]),"=r"((r)[11]),"=r"((r)[12]),"=r"((r)[13]),"=r"((r)[14]),"=r"((r)[15]), \
          "=r"((r)[16]),"=r"((r)[17]),"=r"((r)[18]),"=r"((r)[19]),"=r"((r)[20]),"=r"((r)[21]),"=r"((r)[22]),"=r"((r)[23]), \
          "=r"((r)[24]),"=r"((r)[25]),"=r"((r)[26]),"=r"((r)[27]),"=r"((r)[28]),"=r"((r)[29]),"=r"((r)[30]),"=r"((r)[31]) \
        : "r"(a))

#define STTM_X32(a, r) \
    asm volatile("tcgen05.st.sync.aligned.32x32b.x32.b32 [%0], " \
        "{%1,%2,%3,%4,%5,%6,%7,%8,%9,%10,%11,%12,%13,%14,%15,%16," \
        "%17,%18,%19,%20,%21,%22,%23,%24,%25,%26,%27,%28,%29,%30,%31,%32};" \
        :: "r"(a), \
          "r"((r)[0]),"r"((r)[1]),"r"((r)[2]),"r"((r)[3]),"r"((r)[4]),"r"((r)[5]),"r"((r)[6]),"r"((r)[7]), \
          "r"((r)[8]),"r"((r)[9]),"r"((r)[10]),"r"((r)[11]),"r"((r)[12]),"r"((r)[13]),"r"((r)[14]),"r"((r)[15]), \
          "r"((r)[16]),"r"((r)[17]),"r"((r)[18]),"r"((r)[19]),"r"((r)[20]),"r"((r)[21]),"r"((r)[22]),"r"((r)[23]), \
          "r"((r)[24]),"r"((r)[25]),"r"((r)[26]),"r"((r)[27]),"r"((r)[28]),"r"((r)[29]),"r"((r)[30]),"r"((r)[31]) \
        : "memory")

#define STTM_X16(a, r) \
    asm volatile("tcgen05.st.sync.aligned.32x32b.x16.b32 [%0], " \
        "{%1,%2,%3,%4,%5,%6,%7,%8,%9,%10,%11,%12,%13,%14,%15,%16};" \
        :: "r"(a), \
          "r"((r)[0]),"r"((r)[1]),"r"((r)[2]),"r"((r)[3]),"r"((r)[4]),"r"((r)[5]),"r"((r)[6]),"r"((r)[7]), \
          "r"((r)[8]),"r"((r)[9]),"r"((r)[10]),"r"((r)[11]),"r"((r)[12]),"r"((r)[13]),"r"((r)[14]),"r"((r)[15]) \
        : "memory")

static __device__ __forceinline__ void load_kv(char* smem, int buf,
                                               const float* Kb, const float* Vb, int tid) {
    char* bK_hi = smem + buf * SM_BUFSZ + SM_KHI;
    char* bK_lo = smem + buf * SM_BUFSZ + SM_KLO;
    char* bV_hi = smem + buf * SM_BUFSZ + SM_VHI;
    char* bV_lo = smem + buf * SM_BUFSZ + SM_VLO;
    #pragma unroll
    for (int it = 0; it < 8; it++) {
        int idx = it * NT + tid;
        int n = idx >> 5, c4 = idx & 31, k = c4 * 4;
        float4 u = *(const float4*)(Kb + n * DDIM + k);
        uint32_t h0 = prmt_hi(__float_as_uint(u.x), __float_as_uint(u.y));
        uint32_t h1 = prmt_hi(__float_as_uint(u.z), __float_as_uint(u.w));
        uint32_t l0 = pack_bf2(u.y - trunc_bf(u.y), u.x - trunc_bf(u.x));
        uint32_t l1 = pack_bf2(u.w - trunc_bf(u.w), u.z - trunc_bf(u.z));
        uint32_t o = swz(koff(n, k, BN));
        *(uint2*)(bK_hi + o) = make_uint2(h0, h1);
        *(uint2*)(bK_lo + o) = make_uint2(l0, l1);
    }
    int w = tid >> 5, lid = tid & 31;
    #pragma unroll
    for (int i = 0; i < 4; i++) {
        int p = w * 4 + i;
        #pragma unroll
        for (int j = 0; j < 4; j++) {
            int d = lid + 32 * j;
            float f0 = Vb[(2 * p) * DDIM + d];
            float f1 = Vb[(2 * p + 1) * DDIM + d];
            uint32_t hw = prmt_hi(__float_as_uint(f0), __float_as_uint(f1));
            uint32_t lw = pack_bf2(f1 - trunc_bf(f1), f0 - trunc_bf(f0));
            uint32_t o = swz(((uint32_t)d << 7) + ((uint32_t)p << 2));
            *(uint32_t*)(bV_hi + o) = hw;
            *(uint32_t*)(bV_lo + o) = lw;
        }
    }
}

static __device__ __forceinline__ void issue_g1(uint32_t tmem, uint32_t sb, int buf) {
    const int DOFF[8] = {0, 2, 4, 6, 512, 514, 516, 518};
    uint64_t dh = mk_desc(sb + buf * SM_BUFSZ + SM_KHI);
    uint64_t dl = mk_desc(sb + buf * SM_BUFSZ + SM_KLO);
    #pragma unroll
    for (int ks = 0; ks < 8; ks++)
        mma_f16(tmem + T_S, tmem + T_QHI + ks * 8, dh + DOFF[ks], IDESC_N64, ks != 0);
    #pragma unroll
    for (int ks = 0; ks < 8; ks++)
        mma_f16(tmem + T_S, tmem + T_QHI + ks * 8, dl + DOFF[ks], IDESC_N64, 1);
    #pragma unroll
    for (int ks = 0; ks < 8; ks++)
        mma_f16(tmem + T_S, tmem + T_QLO + ks * 8, dh + DOFF[ks], IDESC_N64, 1);
}

static __device__ __forceinline__ void issue_g2(uint32_t tmem, uint32_t sb, int buf, int first) {
    uint64_t dh = mk_desc(sb + buf * SM_BUFSZ + SM_VHI);
    uint64_t dl = mk_desc(sb + buf * SM_BUFSZ + SM_VLO);
    #pragma unroll
    for (int ks = 0; ks < 4; ks++)
        mma_f16(tmem + T_O, tmem + T_PHI + ks * 8, dh + ks * 2, IDESC_N128, !(first && ks == 0));
    #pragma unroll
    for (int ks = 0; ks < 4; ks++)
        mma_f16(tmem + T_O, tmem + T_PHI + ks * 8, dl + ks * 2, IDESC_N128, 1);
    #pragma unroll
    for (int ks = 0; ks < 4; ks++)
        mma_f16(tmem + T_O, tmem + T_PLO + ks * 8, dh + ks * 2, IDESC_N128, 1);
}
#endif  // TC_DEV

__global__ __launch_bounds__(NT, 1)
void attn_tc_kernel(const float* __restrict__ Qg, const float* __restrict__ Kg,
                    const float* __restrict__ Vg, float* __restrict__ Og) {
#if TC_DEV
    extern __shared__ __align__(1024) char smem[];
    const uint32_t sb = smem_u32(smem);
    const int tid = threadIdx.x;
    const int w = tid >> 5, lid = tid & 31;
    const int sub = w & 3, half = w >> 2;
    const int row = sub * 32 + lid;
    const int bh = blockIdx.y;
    const int q0 = blockIdx.x * BM;

    const float* Qp = Qg + ((size_t)bh * SS + q0) * DDIM;
    const float* Kp = Kg + (size_t)bh * SS * DDIM;
    const float* Vp = Vg + (size_t)bh * SS * DDIM;

    if (w == 0) TMEM_ALLOC(sb + SM_TPTR, TMEM_COLS);
    if (tid == 0) { MBAR_INIT(sb + SM_MB1, 1); MBAR_INIT(sb + SM_MB2, 1); }
    __syncthreads();
    uint32_t tmem;
    asm volatile("ld.shared.b32 %0, [%1];" : "=r"(tmem) : "r"(sb + SM_TPTR));

    if (tid < 128) {
        const float* qr = Qp + tid * DDIM;
        uint32_t woff = ((uint32_t)(tid >> 5)) << 21;
        #pragma unroll
        for (int hb = 0; hb < 2; hb++) {
            uint32_t hi[32], lo[32];
            #pragma unroll
            for (int c4 = 0; c4 < 16; c4++) {
                float4 u = *(const float4*)(qr + hb * 64 + c4 * 4);
                hi[2 * c4]     = prmt_hi(__float_as_uint(u.x), __float_as_uint(u.y));
                hi[2 * c4 + 1] = prmt_hi(__float_as_uint(u.z), __float_as_uint(u.w));
                lo[2 * c4]     = pack_bf2(u.y - trunc_bf(u.y), u.x - trunc_bf(u.x));
                lo[2 * c4 + 1] = pack_bf2(u.w - trunc_bf(u.w), u.z - trunc_bf(u.z));
            }
            STTM_X32(tmem + T_QHI + hb * 32 + woff, hi);
            STTM_X32(tmem + T_QLO + hb * 32 + woff, lo);
        }
        TC_WAIT_ST();
    }
    load_kv(smem, 0, Kp, Vp, tid);
    TC_FENCE_BEFORE();
    __syncthreads();
    if (tid == 0) {
        TC_FENCE_AFTER();
        issue_g1(tmem, sb, 0);
        TC_COMMIT(sb + SM_MB1);
    }

    const float scale = 0.08838834764831845f;
    float dsum = 0.f;
    uint32_t ph1 = 0, ph2 = 0;
    const int c0 = half * 32;

    for (int kb = 0; kb < NKB; kb++) {
        if (kb > 0) { mbar_wait(sb + SM_MB2, ph2); ph2 ^= 1; }
        if (kb < NKB - 1)
            load_kv(smem, (kb + 1) & 1,
                    Kp + (size_t)(kb + 1) * BN * DDIM,
                    Vp + (size_t)(kb + 1) * BN * DDIM, tid);

        mbar_wait(sb + SM_MB1, ph1); ph1 ^= 1;
        TC_FENCE_AFTER();
        uint32_t sr[32];
        LDTM_X32(sr, tmem + T_S + c0);
        TC_WAIT_LD();
        TC_FENCE_BEFORE();
        __syncthreads();
        if (tid == 0 && kb < NKB - 1) {
            TC_FENCE_AFTER();
            issue_g1(tmem, sb, (kb + 1) & 1);
            TC_COMMIT(sb + SM_MB1);
        }

        uint32_t phi[16], plo[16];
        uint32_t base = ((uint32_t)bh << 22) | ((uint32_t)(q0 + row) << 11)
                      | (uint32_t)(kb * BN + c0);
        #pragma unroll 4
        for (int t2 = 0; t2 < 16; t2++) {
            float e0 = __expf(__uint_as_float(sr[2 * t2]) * scale);
            float e1 = __expf(__uint_as_float(sr[2 * t2 + 1]) * scale);
            dsum += e0 + e1;
            float p0 = (tf_word(base + 2 * t2)     & 0x80000000u) ? 0.f : e0;
            float p1 = (tf_word(base + 2 * t2 + 1) & 0x80000000u) ? 0.f : e1;
            phi[t2] = prmt_hi(__float_as_uint(p0), __float_as_uint(p1));
            plo[t2] = pack_bf2(p1 - trunc_bf(p1), p0 - trunc_bf(p0));
        }
        uint32_t woff = ((uint32_t)sub) << 21;
        STTM_X16(tmem + T_PHI + half * 16 + woff, phi);
        STTM_X16(tmem + T_PLO + half * 16 + woff, plo);
        TC_WAIT_ST();
        TC_FENCE_BEFORE();
        __syncthreads();
        if (tid == 0) {
            TC_FENCE_AFTER();
            issue_g2(tmem, sb, kb & 1, kb == 0);
            TC_COMMIT(sb + SM_MB2);
        }
    }

    mbar_wait(sb + SM_MB2, ph2);
    TC_FENCE_AFTER();

    ((float*)(smem + SM_DSUM))[row * 2 + half] = dsum;
    __syncthreads();
    float tot = ((float*)(smem + SM_DSUM))[row * 2]
              + ((float*)(smem + SM_DSUM))[row * 2 + 1];
    float rs = 2.0f / tot;

    size_t orow = ((size_t)bh * SS + (size_t)(q0 + row)) * DDIM;
    #pragma unroll
    for (int hb = 0; hb < 2; hb++) {
        uint32_t orv[32];
        LDTM_X32(orv, tmem + T_O + half * 64 + hb * 32);
        TC_WAIT_LD();
        #pragma unroll
        for (int t = 0; t < 32; t++)
            Og[orow + half * 64 + hb * 32 + t] = __uint_as_float(orv[t]) * rs;
    }
    TC_FENCE_BEFORE();
    __syncthreads();
    if (w == 0) { TMEM_RELINQ(); TMEM_DEALLOC(tmem, TMEM_COLS); }
#else
    // stub — never launched (host dispatch checks register count)
    (void)Qg; (void)Kg; (void)Vg; (void)Og;
#endif
}

// ===========================================================================
// host dispatch: use the tc kernel iff a real sm_103a image was loaded
// ===========================================================================
extern "C" void kernel_launch(void* const* d_in, const int* in_sizes, int n_in,
                              void* d_out, int out_size) {
    (void)in_sizes; (void)n_in; (void)out_size;
    const float* Q = (const float*)d_in[0];
    const float* K = (const float*)d_in[1];
    const float* V = (const float*)d_in[2];
    float* O = (float*)d_out;

    cudaFuncAttributes fa;
    bool tc_ok = (cudaFuncGetAttributes(&fa, attn_tc_kernel) == cudaSuccess)
               && fa.numRegs > 40;   // stub compiles to a handful of regs

    if (tc_ok) {
        cudaFuncSetAttribute(attn_tc_kernel,
                             cudaFuncAttributeMaxDynamicSharedMemorySize, TC_SMEM);
        dim3 grid(SS / BM, 32);
        attn_tc_kernel<<<grid, NT, TC_SMEM>>>(Q, K, V, O);
    } else {
        cudaFuncSetAttribute(attn_dropout_kernel,
                             cudaFuncAttributeMaxDynamicSharedMemorySize, FB_SMEM);
        dim3 grid(SS / FBM, 32);
        attn_dropout_kernel<<<grid, NT, FB_SMEM>>>(Q, K, V, O);
    }
}

// round 5
// speedup vs baseline: 3.0913x; 1.3006x over previous
#include <cuda_runtime.h>
#include <stdint.h>

#define SS 2048
#define DDIM 128
#define NT 256

// ===========================================================================
// threefry-2x32, key=(0,42); jax_threefry_partitionable semantics:
// word(i) = hi ^ lo of threefry2x32(key, ctr=(0, i)); keep iff MSB==0.
// ===========================================================================
static __device__ __forceinline__ uint32_t tf_word(uint32_t idx) {
    const uint32_t K0 = 0u, K1 = 42u, K2 = 0x1BD11BDAu ^ 42u;
    uint32_t x0 = 0u + K0, x1 = idx + K1;
#define TFR(R) { x0 += x1; x1 = __funnelshift_l(x1, x1, (R)); x1 ^= x0; }
    TFR(13) TFR(15) TFR(26) TFR(6)
    x0 += K1; x1 += K2 + 1u;
    TFR(17) TFR(29) TFR(16) TFR(24)
    x0 += K2; x1 += K0 + 2u;
    TFR(13) TFR(15) TFR(26) TFR(6)
    x0 += K0; x1 += K1 + 3u;
    TFR(17) TFR(29) TFR(16) TFR(24)
    x0 += K1; x1 += K2 + 4u;
    TFR(13) TFR(15) TFR(26) TFR(6)
    x0 += K2; x1 += K0 + 5u;
#undef TFR
    return x0 ^ x1;
}

// ===========================================================================
// Fallback SIMT kernel (R2, passed at 2073 us)
// ===========================================================================
#define FBM 64
#define FBN 64
#define SQS 132
#define SPS 68

__global__ __launch_bounds__(NT, 2)
void attn_dropout_kernel(const float* __restrict__ Qg,
                         const float* __restrict__ Kg,
                         const float* __restrict__ Vg,
                         float* __restrict__ Og) {
    extern __shared__ float fsm[];
    float* sQ = fsm;
    float* sK = fsm + FBM * SQS;
    float* sV = fsm + 2 * FBM * SQS;
    float* sP = sK;

    const int tid = threadIdx.x;
    const int tx = tid & 15;
    const int ty = tid >> 4;
    const int bh = blockIdx.y;
    const int q0 = blockIdx.x * FBM;

    const float* Qp = Qg + ((size_t)bh * SS + q0) * DDIM;
    const float* Kp = Kg + (size_t)bh * SS * DDIM;
    const float* Vp = Vg + (size_t)bh * SS * DDIM;

    #pragma unroll
    for (int it = 0; it < (FBM * DDIM) / (4 * NT); it++) {
        int e = (tid + it * NT) * 4;
        int r = e >> 7, c = e & 127;
        *(float4*)(sQ + r * SQS + c) = *(const float4*)(Qp + e);
    }

    float acc[4][8];
    #pragma unroll
    for (int j = 0; j < 4; j++)
        #pragma unroll
        for (int i = 0; i < 8; i++) acc[j][i] = 0.f;
    float dsum[4] = {0.f, 0.f, 0.f, 0.f};
    const float scale = 0.08838834764831845f;

    for (int kb = 0; kb < SS / FBN; kb++) {
        __syncthreads();
        const float* Kb = Kp + (size_t)kb * FBN * DDIM;
        const float* Vb = Vp + (size_t)kb * FBN * DDIM;
        #pragma unroll
        for (int it = 0; it < (FBN * DDIM) / (4 * NT); it++) {
            int e = (tid + it * NT) * 4;
            int r = e >> 7, c = e & 127;
            *(float4*)(sK + r * SQS + c) = *(const float4*)(Kb + e);
            *(float4*)(sV + r * DDIM + c) = *(const float4*)(Vb + e);
        }
        __syncthreads();

        float sacc[4][4];
        #pragma unroll
        for (int j = 0; j < 4; j++)
            #pragma unroll
            for (int i = 0; i < 4; i++) sacc[j][i] = 0.f;

        #pragma unroll 4
        for (int d0 = 0; d0 < DDIM; d0 += 4) {
            float4 aq[4], bk[4];
            #pragma unroll
            for (int j = 0; j < 4; j++)
                aq[j] = *(const float4*)(sQ + (4 * ty + j) * SQS + d0);
            #pragma unroll
            for (int i = 0; i < 4; i++)
                bk[i] = *(const float4*)(sK + (tx + 16 * i) * SQS + d0);
            #pragma unroll
            for (int j = 0; j < 4; j++)
                #pragma unroll
                for (int i = 0; i < 4; i++)
                    sacc[j][i] += aq[j].x * bk[i].x + aq[j].y * bk[i].y
                                + aq[j].z * bk[i].z + aq[j].w * bk[i].w;
        }
        __syncthreads();

        uint32_t baseIdx = ((uint32_t)bh << 22) | ((uint32_t)q0 << 11)
                         | (uint32_t)(kb * FBN);
        #pragma unroll
        for (int j = 0; j < 4; j++) {
            #pragma unroll
            for (int i = 0; i < 4; i++) {
                float ex = __expf(sacc[j][i] * scale);
                dsum[j] += ex;
                uint32_t idx = baseIdx + ((uint32_t)(4 * ty + j) << 11)
                             + (uint32_t)(tx + 16 * i);
                uint32_t w = tf_word(idx);
                sP[(4 * ty + j) * SPS + (tx + 16 * i)] = (w & 0x80000000u) ? 0.f : ex;
            }
        }
        __syncthreads();

        #pragma unroll 2
        for (int c0 = 0; c0 < FBN; c0 += 4) {
            float4 p4[4];
            #pragma unroll
            for (int j = 0; j < 4; j++)
                p4[j] = *(const float4*)(sP + (4 * ty + j) * SPS + c0);
            #pragma unroll
            for (int cc = 0; cc < 4; cc++) {
                float bb[8];
                #pragma unroll
                for (int i = 0; i < 8; i++)
                    bb[i] = sV[(c0 + cc) * DDIM + tx + 16 * i];
                #pragma unroll
                for (int j = 0; j < 4; j++) {
                    float pj = ((const float*)&p4[j])[cc];
                    #pragma unroll
                    for (int i = 0; i < 8; i++)
                        acc[j][i] += pj * bb[i];
                }
            }
        }
    }

    __syncthreads();
    #pragma unroll
    for (int j = 0; j < 4; j++)
        sP[(4 * ty + j) * SPS + tx] = dsum[j];
    __syncthreads();

    #pragma unroll
    for (int j = 0; j < 4; j++) {
        float s = 0.f;
        #pragma unroll
        for (int t = 0; t < 16; t++) s += sP[(4 * ty + j) * SPS + t];
        float rs = 2.0f / s;
        size_t orow = ((size_t)bh * SS + (size_t)(q0 + 4 * ty + j)) * DDIM;
        #pragma unroll
        for (int i = 0; i < 8; i++)
            Og[orow + tx + 16 * i] = acc[j][i] * rs;
    }
}

#define FB_SMEM ((2 * FBM * SQS + FBN * DDIM) * 4)

// ===========================================================================
// common helpers (no arch-specific instructions)
// ===========================================================================
#define BM 128
#define BN 64
#define NKB (SS / BN)

static __device__ __forceinline__ uint32_t smem_u32(const void* p) {
    uint32_t a;
    asm("{ .reg .u64 t; cvta.to.shared.u64 t, %1; cvt.u32.u64 %0, t; }" : "=r"(a) : "l"(p));
    return a;
}
static __device__ __forceinline__ uint32_t swz(uint32_t o) { return o ^ ((o >> 3) & 0x70u); }
static __device__ __forceinline__ uint32_t koff(int n, int k, int nrows) {
    return ((uint32_t)((n >> 3) + ((k >> 6) * (nrows >> 3))) << 10)
         + (((uint32_t)n & 7u) << 7) + (((uint32_t)k & 63u) << 1);
}
static __device__ __forceinline__ uint32_t prmt_hi(uint32_t a, uint32_t b) {
    uint32_t r; asm("prmt.b32 %0,%1,%2,0x7632;" : "=r"(r) : "r"(a), "r"(b)); return r;
}
static __device__ __forceinline__ float trunc_bf(float x) {
    return __uint_as_float(__float_as_uint(x) & 0xffff0000u);
}
static __device__ __forceinline__ uint32_t pack_bf2(float hi_elem, float lo_elem) {
    uint32_t r; asm("cvt.rn.bf16x2.f32 %0,%1,%2;" : "=r"(r) : "f"(hi_elem), "f"(lo_elem)); return r;
}

// smem byte offsets (also the blob tile layout)
#define SM_BUFSZ 65536
#define SM_KHI 0
#define SM_KLO 16384
#define SM_VHI 32768
#define SM_VLO 49152
#define SM_DSUM 131072
#define SM_TPTR 133120
#define SM_MB1  133128
#define SM_MB2  133136
#define TC_SMEM 133184

// pre-converted bf16 hi/lo K/V tiles: 32 bh x 32 kb x 64KB = 64 MiB
__device__ __align__(1024) unsigned char g_blob[32 * 32 * SM_BUFSZ];

// ===========================================================================
// pre-kernel: fp32 K/V -> bf16 hi/lo tile blobs in MMA-swizzled smem layout
// ===========================================================================
__global__ __launch_bounds__(256)
void prep_kv_kernel(const float* __restrict__ Kg, const float* __restrict__ Vg) {
    const int tile = blockIdx.x;            // bh*32 + kb
    const int bh = tile >> 5, kb = tile & 31;
    const int tid = threadIdx.x;
    const float* Kb = Kg + ((size_t)bh * SS + (size_t)kb * BN) * DDIM;
    const float* Vb = Vg + ((size_t)bh * SS + (size_t)kb * BN) * DDIM;
    unsigned char* out = g_blob + ((size_t)tile << 16);

    #pragma unroll
    for (int it = 0; it < 8; it++) {
        int idx = it * 256 + tid;
        int n = idx >> 5, k = (idx & 31) * 4;
        float4 u = *(const float4*)(Kb + n * DDIM + k);
        uint32_t h0 = prmt_hi(__float_as_uint(u.x), __float_as_uint(u.y));
        uint32_t h1 = prmt_hi(__float_as_uint(u.z), __float_as_uint(u.w));
        uint32_t l0 = pack_bf2(u.y - trunc_bf(u.y), u.x - trunc_bf(u.x));
        uint32_t l1 = pack_bf2(u.w - trunc_bf(u.w), u.z - trunc_bf(u.z));
        uint32_t o = swz(koff(n, k, BN));
        *(uint2*)(out + SM_KHI + o) = make_uint2(h0, h1);
        *(uint2*)(out + SM_KLO + o) = make_uint2(l0, l1);
    }
    int w = tid >> 5, lid = tid & 31;
    #pragma unroll
    for (int i = 0; i < 4; i++) {
        int p = w * 4 + i;
        #pragma unroll
        for (int j = 0; j < 4; j++) {
            int d = lid + 32 * j;
            float f0 = Vb[(2 * p) * DDIM + d];
            float f1 = Vb[(2 * p + 1) * DDIM + d];
            uint32_t hw = prmt_hi(__float_as_uint(f0), __float_as_uint(f1));
            uint32_t lw = pack_bf2(f1 - trunc_bf(f1), f0 - trunc_bf(f0));
            uint32_t o = swz(((uint32_t)d << 7) + ((uint32_t)p << 2));
            *(uint32_t*)(out + SM_VHI + o) = hw;
            *(uint32_t*)(out + SM_VLO + o) = lw;
        }
    }
}

// ===========================================================================
// tcgen05 kernel — only real on the sm_103a pass
// ===========================================================================
#if !defined(__CUDA_ARCH__) || defined(__CUDA_ARCH_FEAT_SM103_ALL) || \
    (defined(__CUDA_ARCH_SPECIFIC__) && (__CUDA_ARCH_SPECIFIC__ >= 1000))
#define TC_PATH_COMPILED 1
#else
#define TC_PATH_COMPILED 0
#endif
#if defined(__CUDA_ARCH__) && TC_PATH_COMPILED
#define TC_DEV 1
#else
#define TC_DEV 0
#endif

#define T_QHI 0
#define T_QLO 64
#define T_S   128
#define T_PHI 192
#define T_PLO 224
#define T_O   256
#define TMEM_COLS 512

#define IDESC_N64  0x8100490u
#define IDESC_N128 0x8200490u

static constexpr uint64_t DESC_BASE =
    (uint64_t(2) << 61) | (uint64_t(1) << 46) | (uint64_t(64) << 32) | (uint64_t(1) << 16);
static __device__ __forceinline__ uint64_t mk_desc(uint32_t addr) {
    return DESC_BASE | ((uint64_t)(addr >> 4) & 0x3FFFull);
}

#if TC_DEV
static __device__ __forceinline__ void mma_f16(uint32_t d, uint32_t a, uint64_t bdesc,
                                               uint32_t idesc, int acc) {
    asm volatile(
        "{\n\t.reg .pred p;\n\tsetp.ne.u32 p,%5,0;\n\t"
        "tcgen05.mma.cta_group::1.kind::f16 [%0],[%1],%2,%3,{%4,%4,%4,%4},p;\n\t}"
        :: "r"(d), "r"(a), "l"(bdesc), "r"(idesc), "r"(0u), "r"((uint32_t)acc) : "memory");
}

#define TMEM_ALLOC(sa, n)  asm volatile("tcgen05.alloc.cta_group::1.sync.aligned.shared::cta.b32 [%0], %1;" :: "r"(sa), "r"((uint32_t)(n)) : "memory")
#define TMEM_DEALLOC(t, n) asm volatile("tcgen05.dealloc.cta_group::1.sync.aligned.b32 %0, %1;" :: "r"(t), "r"((uint32_t)(n)))
#define TMEM_RELINQ()      asm volatile("tcgen05.relinquish_alloc_permit.cta_group::1.sync.aligned;")
#define TC_COMMIT(mb)      asm volatile("tcgen05.commit.cta_group::1.mbarrier::arrive::one.shared::cluster.b64 [%0];" :: "r"(mb) : "memory")
#define TC_WAIT_LD()       asm volatile("tcgen05.wait::ld.sync.aligned;" ::: "memory")
#define TC_WAIT_ST()       asm volatile("tcgen05.wait::st.sync.aligned;" ::: "memory")
#define TC_FENCE_BEFORE()  asm volatile("tcgen05.fence::before_thread_sync;" ::: "memory")
#define TC_FENCE_AFTER()   asm volatile("tcgen05.fence::after_thread_sync;" ::: "memory")
#define MBAR_INIT(mb, c)   asm volatile("mbarrier.init.shared.b64 [%0], %1;" :: "r"(mb), "r"((uint32_t)(c)) : "memory")
#define CP_ASYNC16(dst, src) asm volatile("cp.async.cg.shared.global [%0], [%1], 16;" :: "r"(dst), "l"(src) : "memory")
#define CP_COMMIT()        asm volatile("cp.async.commit_group;" ::: "memory")
#define CP_WAIT0()         asm volatile("cp.async.wait_group 0;" ::: "memory")
#define FENCE_PROXY()      asm volatile("fence.proxy.async.shared::cta;" ::: "memory")

static __device__ __forceinline__ void mbar_wait(uint32_t mb, uint32_t parity) {
    asm volatile(
        "{\n\t.reg .pred P;\n\t"
        "W%=:\n\tmbarrier.try_wait.parity.acquire.cta.shared::cta.b64 P, [%0], %1, 0x989680;\n\t"
        "@P bra.uni D%=;\n\tbra.uni W%=;\n\tD%=:\n\t}"
        :: "r"(mb), "r"(parity) : "memory");
}

#define LDTM_X16(r, a) \
    asm volatile("tcgen05.ld.sync.aligned.32x32b.x16.b32 " \
        "{%0,%1,%2,%3,%4,%5,%6,%7,%8,%9,%10,%11,%12,%13,%14,%15}, [%16];" \
        : "=r"((r)[0]),"=r"((r)[1]),"=r"((r)[2]),"=r"((r)[3]),"=r"((r)[4]),"=r"((r)[5]),"=r"((r)[6]),"=r"((r)[7]), \
          "=r"((r)[8]),"=r"((r)[9]),"=r"((r)[10]),"=r"((r)[11]),"=r"((r)[12]),"=r"((r)[13]),"=r"((r)[14]),"=r"((r)[15]) \
        : "r"(a))

#define LDTM_X32(r, a) \
    asm volatile("tcgen05.ld.sync.aligned.32x32b.x32.b32 " \
        "{%0,%1,%2,%3,%4,%5,%6,%7,%8,%9,%10,%11,%12,%13,%14,%15," \
        "%16,%17,%18,%19,%20,%21,%22,%23,%24,%25,%26,%27,%28,%29,%30,%31}, [%32];" \
        : "=r"((r)[0]),"=r"((r)[1]),"=r"((r)[2]),"=r"((r)[3]),"=r"((r)[4]),"=r"((r)[5]),"=r"((r)[6]),"=r"((r)[7]), \
          "=r"((r)[8]),"=r"((r)[9]),"=r"((r)[10]),"=r"((r)[11]),"=r"((r)[12]),"=r"((r)[13]),"=r"((r)[14]),"=r"((r)[15]), \
          "=r"((r)[16]),"=r"((r)[17]),"=r"((r)[18]),"=r"((r)[19]),"=r"((r)[20]),"=r"((r)[21]),"=r"((r)[22]),"=r"((r)[23]), \
          "=r"((r)[24]),"=r"((r)[25]),"=r"((r)[26]),"=r"((r)[27]),"=r"((r)[28]),"=r"((r)[29]),"=r"((r)[30]),"=r"((r)[31]) \
        : "r"(a))

#define STTM_X8(a, r) \
    asm volatile("tcgen05.st.sync.aligned.32x32b.x8.b32 [%0], " \
        "{%1,%2,%3,%4,%5,%6,%7,%8};" \
        :: "r"(a), \
          "r"((r)[0]),"r"((r)[1]),"r"((r)[2]),"r"((r)[3]),"r"((r)[4]),"r"((r)[5]),"r"((r)[6]),"r"((r)[7]) \
        : "memory")

#define STTM_X16(a, r) \
    asm volatile("tcgen05.st.sync.aligned.32x32b.x16.b32 [%0], " \
        "{%1,%2,%3,%4,%5,%6,%7,%8,%9,%10,%11,%12,%13,%14,%15,%16};" \
        :: "r"(a), \
          "r"((r)[0]),"r"((r)[1]),"r"((r)[2]),"r"((r)[3]),"r"((r)[4]),"r"((r)[5]),"r"((r)[6]),"r"((r)[7]), \
          "r"((r)[8]),"r"((r)[9]),"r"((r)[10]),"r"((r)[11]),"r"((r)[12]),"r"((r)[13]),"r"((r)[14]),"r"((r)[15]) \
        : "memory")

// 64KB blob -> smem, 128 threads x 32 x 16B, coalesced
static __device__ __forceinline__ void copy_blob(uint32_t dst, const unsigned char* src, int t) {
    #pragma unroll
    for (int i = 0; i < 32; i++) {
        uint32_t off = (uint32_t)((i * 128 + t) * 16);
        CP_ASYNC16(dst + off, src + off);
    }
    CP_COMMIT();
}

static __device__ __forceinline__ void issue_g1(uint32_t tmem, uint32_t sb, int buf) {
    const int DOFF[8] = {0, 2, 4, 6, 512, 514, 516, 518};
    uint64_t dh = mk_desc(sb + buf * SM_BUFSZ + SM_KHI);
    uint64_t dl = mk_desc(sb + buf * SM_BUFSZ + SM_KLO);
    #pragma unroll
    for (int ks = 0; ks < 8; ks++)
        mma_f16(tmem + T_S, tmem + T_QHI + ks * 8, dh + DOFF[ks], IDESC_N64, ks != 0);
    #pragma unroll
    for (int ks = 0; ks < 8; ks++)
        mma_f16(tmem + T_S, tmem + T_QHI + ks * 8, dl + DOFF[ks], IDESC_N64, 1);
    #pragma unroll
    for (int ks = 0; ks < 8; ks++)
        mma_f16(tmem + T_S, tmem + T_QLO + ks * 8, dh + DOFF[ks], IDESC_N64, 1);
}

static __device__ __forceinline__ void issue_g2(uint32_t tmem, uint32_t sb, int buf, int first) {
    uint64_t dh = mk_desc(sb + buf * SM_BUFSZ + SM_VHI);
    uint64_t dl = mk_desc(sb + buf * SM_BUFSZ + SM_VLO);
    #pragma unroll
    for (int ks = 0; ks < 4; ks++)
        mma_f16(tmem + T_O, tmem + T_PHI + ks * 8, dh + ks * 2, IDESC_N128, !(first && ks == 0));
    #pragma unroll
    for (int ks = 0; ks < 4; ks++)
        mma_f16(tmem + T_O, tmem + T_PHI + ks * 8, dl + ks * 2, IDESC_N128, 1);
    #pragma unroll
    for (int ks = 0; ks < 4; ks++)
        mma_f16(tmem + T_O, tmem + T_PLO + ks * 8, dh + ks * 2, IDESC_N128, 1);
}
#endif  // TC_DEV

__global__ __launch_bounds__(512, 1)
void attn_tc_kernel(const float* __restrict__ Qg, float* __restrict__ Og) {
#if TC_DEV
    extern __shared__ __align__(1024) char smem[];
    const uint32_t sb = smem_u32(smem);
    const int tid = threadIdx.x;
    const int w = tid >> 5, lane = tid & 31;
    const int sub = w & 3, q = w >> 2;        // q = column quarter 0..3
    const int row = sub * 32 + lane;
    const int bh = blockIdx.y;
    const int q0 = blockIdx.x * BM;
    const float* Qp = Qg + ((size_t)bh * SS + q0) * DDIM;
    const unsigned char* blob = g_blob + ((size_t)(bh * NKB) << 16);

    if (w == 0) TMEM_ALLOC(sb + SM_TPTR, TMEM_COLS);
    if (tid == 0) { MBAR_INIT(sb + SM_MB1, 1); MBAR_INIT(sb + SM_MB2, 1); }
    __syncthreads();
    uint32_t tmem;
    asm volatile("ld.shared.b32 %0, [%1];" : "=r"(tmem) : "r"(sb + SM_TPTR));

    // ---- prologue: buf0 copy + Q -> TMEM (threads 0-127) ----
    if (tid < 128) {
        copy_blob(sb + 0, blob, tid);
        const float* qr = Qp + tid * DDIM;
        uint32_t woff = ((uint32_t)((tid >> 5) & 3)) << 21;
        #pragma unroll
        for (int hb = 0; hb < 4; hb++) {
            uint32_t hi[16], lo[16];
            #pragma unroll
            for (int c4 = 0; c4 < 8; c4++) {
                float4 u = *(const float4*)(qr + hb * 32 + c4 * 4);
                hi[2 * c4]     = prmt_hi(__float_as_uint(u.x), __float_as_uint(u.y));
                hi[2 * c4 + 1] = prmt_hi(__float_as_uint(u.z), __float_as_uint(u.w));
                lo[2 * c4]     = pack_bf2(u.y - trunc_bf(u.y), u.x - trunc_bf(u.x));
                lo[2 * c4 + 1] = pack_bf2(u.w - trunc_bf(u.w), u.z - trunc_bf(u.z));
            }
            STTM_X16(tmem + T_QHI + hb * 16 + woff, hi);
            STTM_X16(tmem + T_QLO + hb * 16 + woff, lo);
        }
        TC_WAIT_ST();
    }
    CP_WAIT0();
    FENCE_PROXY();
    TC_FENCE_BEFORE();
    __syncthreads();
    if (tid == 0) {
        TC_FENCE_AFTER();
        issue_g1(tmem, sb, 0);
        TC_COMMIT(sb + SM_MB1);
    }

    const float scale = 0.08838834764831845f;  // 1/sqrt(128)
    float dsum = 0.f;

    for (int kb = 0; kb < NKB; kb++) {
        // A: warps 0-3 prefetch next KV blob (after GEMM2(kb-1) frees the buffer)
        if (tid < 128) {
            if (kb > 0) mbar_wait(sb + SM_MB2, (kb - 1) & 1);
            if (kb < NKB - 1)
                copy_blob(sb + (((kb + 1) & 1) ? SM_BUFSZ : 0),
                          blob + ((size_t)(kb + 1) << 16), tid);
        }
        // B: threefry mask bits (index-only; overlaps GEMM1(kb))
        uint32_t base = ((uint32_t)bh << 22) | ((uint32_t)(q0 + row) << 11)
                      | (uint32_t)(kb * BN + q * 16);
        uint32_t mbits = 0;
        #pragma unroll
        for (int t = 0; t < 16; t++)
            mbits |= (tf_word(base + t) >> 31) << t;
        // C: S ready -> LDTM
        mbar_wait(sb + SM_MB1, kb & 1);
        TC_FENCE_AFTER();
        uint32_t sr[16];
        LDTM_X16(sr, tmem + T_S + q * 16);
        TC_WAIT_LD();
        TC_FENCE_BEFORE();
        // D: copies done + smem visible to MMA; S tile free
        CP_WAIT0();
        FENCE_PROXY();
        __syncthreads();
        // E: launch next GEMM1 into freed S
        if (tid == 0 && kb < NKB - 1) {
            TC_FENCE_AFTER();
            issue_g1(tmem, sb, (kb + 1) & 1);
            TC_COMMIT(sb + SM_MB1);
        }
        // F: exp + mask + bf16 split -> P
        uint32_t phi[8], plo[8];
        #pragma unroll
        for (int t2 = 0; t2 < 8; t2++) {
            float e0 = __expf(__uint_as_float(sr[2 * t2]) * scale);
            float e1 = __expf(__uint_as_float(sr[2 * t2 + 1]) * scale);
            dsum += e0 + e1;
            float p0 = (mbits & (1u << (2 * t2)))     ? 0.f : e0;
            float p1 = (mbits & (1u << (2 * t2 + 1))) ? 0.f : e1;
            phi[t2] = prmt_hi(__float_as_uint(p0), __float_as_uint(p1));
            plo[t2] = pack_bf2(p1 - trunc_bf(p1), p0 - trunc_bf(p0));
        }
        uint32_t woff = ((uint32_t)sub) << 21;
        STTM_X8(tmem + T_PHI + q * 8 + woff, phi);
        STTM_X8(tmem + T_PLO + q * 8 + woff, plo);
        TC_WAIT_ST();
        TC_FENCE_BEFORE();
        __syncthreads();
        // G: launch GEMM2
        if (tid == 0) {
            TC_FENCE_AFTER();
            issue_g2(tmem, sb, kb & 1, kb == 0);
            TC_COMMIT(sb + SM_MB2);
        }
    }

    mbar_wait(sb + SM_MB2, (NKB - 1) & 1);
    TC_FENCE_AFTER();

    // denominator reduce across the 4 column quarters
    ((float*)(smem + SM_DSUM))[row * 4 + q] = dsum;
    __syncthreads();
    float tot = 0.f;
    #pragma unroll
    for (int i = 0; i < 4; i++)
        tot += ((float*)(smem + SM_DSUM))[row * 4 + i];
    float rs = 2.0f / tot;   // dropout 1/(1-p)=2 folded in

    uint32_t orv[32];
    LDTM_X32(orv, tmem + T_O + q * 32);
    TC_WAIT_LD();
    TC_FENCE_BEFORE();
    size_t orow = ((size_t)bh * SS + (size_t)(q0 + row)) * DDIM;
    #pragma unroll
    for (int t = 0; t < 32; t++)
        Og[orow + q * 32 + t] = __uint_as_float(orv[t]) * rs;

    __syncthreads();
    if (w == 0) { TMEM_RELINQ(); TMEM_DEALLOC(tmem, TMEM_COLS); }
#else
    (void)Qg; (void)Og;
#endif
}

// ===========================================================================
// host dispatch
// ===========================================================================
extern "C" void kernel_launch(void* const* d_in, const int* in_sizes, int n_in,
                              void* d_out, int out_size) {
    (void)in_sizes; (void)n_in; (void)out_size;
    const float* Q = (const float*)d_in[0];
    const float* K = (const float*)d_in[1];
    const float* V = (const float*)d_in[2];
    float* O = (float*)d_out;

    cudaFuncAttributes fa;
    bool tc_ok = (cudaFuncGetAttributes(&fa, attn_tc_kernel) == cudaSuccess)
               && fa.numRegs > 40;

    if (tc_ok) {
        prep_kv_kernel<<<1024, 256>>>(K, V);
        cudaFuncSetAttribute(attn_tc_kernel,
                             cudaFuncAttributeMaxDynamicSharedMemorySize, TC_SMEM);
        dim3 grid(SS / BM, 32);
        attn_tc_kernel<<<grid, 512, TC_SMEM>>>(Q, O);
    } else {
        cudaFuncSetAttribute(attn_dropout_kernel,
                             cudaFuncAttributeMaxDynamicSharedMemorySize, FB_SMEM);
        dim3 grid(SS / FBM, 32);
        attn_dropout_kernel<<<grid, NT, FB_SMEM>>>(Q, K, V, O);
    }
}

// round 6
// speedup vs baseline: 3.2338x; 1.0461x over previous
#include <cuda_runtime.h>
#include <stdint.h>

#define SS 2048
#define DDIM 128
#define NT 256

// ===========================================================================
// threefry-2x32, key=(0,42); jax_threefry_partitionable semantics:
// word(i) = hi ^ lo of threefry2x32(key, ctr=(0, i)); keep iff MSB==0.
// ===========================================================================
static __device__ __forceinline__ uint32_t tf_word(uint32_t idx) {
    const uint32_t K0 = 0u, K1 = 42u, K2 = 0x1BD11BDAu ^ 42u;
    uint32_t x0 = 0u + K0, x1 = idx + K1;
#define TFR(R) { x0 += x1; x1 = __funnelshift_l(x1, x1, (R)); x1 ^= x0; }
    TFR(13) TFR(15) TFR(26) TFR(6)
    x0 += K1; x1 += K2 + 1u;
    TFR(17) TFR(29) TFR(16) TFR(24)
    x0 += K2; x1 += K0 + 2u;
    TFR(13) TFR(15) TFR(26) TFR(6)
    x0 += K0; x1 += K1 + 3u;
    TFR(17) TFR(29) TFR(16) TFR(24)
    x0 += K1; x1 += K2 + 4u;
    TFR(13) TFR(15) TFR(26) TFR(6)
    x0 += K2; x1 += K0 + 5u;
#undef TFR
    return x0 ^ x1;
}

// ===========================================================================
// Fallback SIMT kernel (R2, passed at 2073 us)
// ===========================================================================
#define FBM 64
#define FBN 64
#define SQS 132
#define SPS 68

__global__ __launch_bounds__(NT, 2)
void attn_dropout_kernel(const float* __restrict__ Qg,
                         const float* __restrict__ Kg,
                         const float* __restrict__ Vg,
                         float* __restrict__ Og) {
    extern __shared__ float fsm[];
    float* sQ = fsm;
    float* sK = fsm + FBM * SQS;
    float* sV = fsm + 2 * FBM * SQS;
    float* sP = sK;

    const int tid = threadIdx.x;
    const int tx = tid & 15;
    const int ty = tid >> 4;
    const int bh = blockIdx.y;
    const int q0 = blockIdx.x * FBM;

    const float* Qp = Qg + ((size_t)bh * SS + q0) * DDIM;
    const float* Kp = Kg + (size_t)bh * SS * DDIM;
    const float* Vp = Vg + (size_t)bh * SS * DDIM;

    #pragma unroll
    for (int it = 0; it < (FBM * DDIM) / (4 * NT); it++) {
        int e = (tid + it * NT) * 4;
        int r = e >> 7, c = e & 127;
        *(float4*)(sQ + r * SQS + c) = *(const float4*)(Qp + e);
    }

    float acc[4][8];
    #pragma unroll
    for (int j = 0; j < 4; j++)
        #pragma unroll
        for (int i = 0; i < 8; i++) acc[j][i] = 0.f;
    float dsum[4] = {0.f, 0.f, 0.f, 0.f};
    const float scale = 0.08838834764831845f;

    for (int kb = 0; kb < SS / FBN; kb++) {
        __syncthreads();
        const float* Kb = Kp + (size_t)kb * FBN * DDIM;
        const float* Vb = Vp + (size_t)kb * FBN * DDIM;
        #pragma unroll
        for (int it = 0; it < (FBN * DDIM) / (4 * NT); it++) {
            int e = (tid + it * NT) * 4;
            int r = e >> 7, c = e & 127;
            *(float4*)(sK + r * SQS + c) = *(const float4*)(Kb + e);
            *(float4*)(sV + r * DDIM + c) = *(const float4*)(Vb + e);
        }
        __syncthreads();

        float sacc[4][4];
        #pragma unroll
        for (int j = 0; j < 4; j++)
            #pragma unroll
            for (int i = 0; i < 4; i++) sacc[j][i] = 0.f;

        #pragma unroll 4
        for (int d0 = 0; d0 < DDIM; d0 += 4) {
            float4 aq[4], bk[4];
            #pragma unroll
            for (int j = 0; j < 4; j++)
                aq[j] = *(const float4*)(sQ + (4 * ty + j) * SQS + d0);
            #pragma unroll
            for (int i = 0; i < 4; i++)
                bk[i] = *(const float4*)(sK + (tx + 16 * i) * SQS + d0);
            #pragma unroll
            for (int j = 0; j < 4; j++)
                #pragma unroll
                for (int i = 0; i < 4; i++)
                    sacc[j][i] += aq[j].x * bk[i].x + aq[j].y * bk[i].y
                                + aq[j].z * bk[i].z + aq[j].w * bk[i].w;
        }
        __syncthreads();

        uint32_t baseIdx = ((uint32_t)bh << 22) | ((uint32_t)q0 << 11)
                         | (uint32_t)(kb * FBN);
        #pragma unroll
        for (int j = 0; j < 4; j++) {
            #pragma unroll
            for (int i = 0; i < 4; i++) {
                float ex = __expf(sacc[j][i] * scale);
                dsum[j] += ex;
                uint32_t idx = baseIdx + ((uint32_t)(4 * ty + j) << 11)
                             + (uint32_t)(tx + 16 * i);
                uint32_t w = tf_word(idx);
                sP[(4 * ty + j) * SPS + (tx + 16 * i)] = (w & 0x80000000u) ? 0.f : ex;
            }
        }
        __syncthreads();

        #pragma unroll 2
        for (int c0 = 0; c0 < FBN; c0 += 4) {
            float4 p4[4];
            #pragma unroll
            for (int j = 0; j < 4; j++)
                p4[j] = *(const float4*)(sP + (4 * ty + j) * SPS + c0);
            #pragma unroll
            for (int cc = 0; cc < 4; cc++) {
                float bb[8];
                #pragma unroll
                for (int i = 0; i < 8; i++)
                    bb[i] = sV[(c0 + cc) * DDIM + tx + 16 * i];
                #pragma unroll
                for (int j = 0; j < 4; j++) {
                    float pj = ((const float*)&p4[j])[cc];
                    #pragma unroll
                    for (int i = 0; i < 8; i++)
                        acc[j][i] += pj * bb[i];
                }
            }
        }
    }

    __syncthreads();
    #pragma unroll
    for (int j = 0; j < 4; j++)
        sP[(4 * ty + j) * SPS + tx] = dsum[j];
    __syncthreads();

    #pragma unroll
    for (int j = 0; j < 4; j++) {
        float s = 0.f;
        #pragma unroll
        for (int t = 0; t < 16; t++) s += sP[(4 * ty + j) * SPS + t];
        float rs = 2.0f / s;
        size_t orow = ((size_t)bh * SS + (size_t)(q0 + 4 * ty + j)) * DDIM;
        #pragma unroll
        for (int i = 0; i < 8; i++)
            Og[orow + tx + 16 * i] = acc[j][i] * rs;
    }
}

#define FB_SMEM ((2 * FBM * SQS + FBN * DDIM) * 4)

// ===========================================================================
// common helpers
// ===========================================================================
#define BM 128
#define BN 64
#define NKB (SS / BN)

static __device__ __forceinline__ uint32_t smem_u32(const void* p) {
    uint32_t a;
    asm("{ .reg .u64 t; cvta.to.shared.u64 t, %1; cvt.u32.u64 %0, t; }" : "=r"(a) : "l"(p));
    return a;
}
static __device__ __forceinline__ uint32_t swz(uint32_t o) { return o ^ ((o >> 3) & 0x70u); }
static __device__ __forceinline__ uint32_t koff(int n, int k, int nrows) {
    return ((uint32_t)((n >> 3) + ((k >> 6) * (nrows >> 3))) << 10)
         + (((uint32_t)n & 7u) << 7) + (((uint32_t)k & 63u) << 1);
}
static __device__ __forceinline__ uint32_t prmt_hi(uint32_t a, uint32_t b) {
    uint32_t r; asm("prmt.b32 %0,%1,%2,0x7632;" : "=r"(r) : "r"(a), "r"(b)); return r;
}
static __device__ __forceinline__ float trunc_bf(float x) {
    return __uint_as_float(__float_as_uint(x) & 0xffff0000u);
}
static __device__ __forceinline__ uint32_t pack_bf2(float hi_elem, float lo_elem) {
    uint32_t r; asm("cvt.rn.bf16x2.f32 %0,%1,%2;" : "=r"(r) : "f"(hi_elem), "f"(lo_elem)); return r;
}

// smem byte offsets (also the blob tile layout)
#define SM_BUFSZ 65536
#define SM_KHI 0
#define SM_KLO 16384
#define SM_VHI 32768
#define SM_VLO 49152
#define SM_DSUM 131072          /* 128 rows x 8 octs x 4B = 4096 */
#define SM_TPTR 135168
#define SM_MB1  135176
#define SM_MB2  135184
#define TC_SMEM 135232

// pre-converted bf16 hi/lo K/V tiles: 32 bh x 32 kb x 64KB = 64 MiB
__device__ __align__(1024) unsigned char g_blob[32 * 32 * SM_BUFSZ];

// ===========================================================================
// pre-kernel: fp32 K/V -> bf16 hi/lo tile blobs in MMA-swizzled smem layout
// V^T staged through smem so gmem writes are coalesced float4s.
// ===========================================================================
__global__ __launch_bounds__(256)
void prep_kv_kernel(const float* __restrict__ Kg, const float* __restrict__ Vg) {
    __shared__ __align__(16) unsigned char vs[32768];   // VHI | VLO staged
    const int tile = blockIdx.x;            // bh*32 + kb
    const int bh = tile >> 5, kb = tile & 31;
    const int tid = threadIdx.x;
    const float* Kb = Kg + ((size_t)bh * SS + (size_t)kb * BN) * DDIM;
    const float* Vb = Vg + ((size_t)bh * SS + (size_t)kb * BN) * DDIM;
    unsigned char* out = g_blob + ((size_t)tile << 16);

    // K: direct (writes land in whole 128B sectors)
    #pragma unroll
    for (int it = 0; it < 8; it++) {
        int idx = it * 256 + tid;
        int n = idx >> 5, k = (idx & 31) * 4;
        float4 u = *(const float4*)(Kb + n * DDIM + k);
        uint32_t h0 = prmt_hi(__float_as_uint(u.x), __float_as_uint(u.y));
        uint32_t h1 = prmt_hi(__float_as_uint(u.z), __float_as_uint(u.w));
        uint32_t l0 = pack_bf2(u.y - trunc_bf(u.y), u.x - trunc_bf(u.x));
        uint32_t l1 = pack_bf2(u.w - trunc_bf(u.w), u.z - trunc_bf(u.z));
        uint32_t o = swz(koff(n, k, BN));
        *(uint2*)(out + SM_KHI + o) = make_uint2(h0, h1);
        *(uint2*)(out + SM_KLO + o) = make_uint2(l0, l1);
    }
    // V^T into smem staging (scattered 4B stores hit smem, not gmem)
    int w = tid >> 5, lid = tid & 31;
    #pragma unroll
    for (int i = 0; i < 4; i++) {
        int p = w * 4 + i;
        #pragma unroll
        for (int j = 0; j < 4; j++) {
            int d = lid + 32 * j;
            float f0 = Vb[(2 * p) * DDIM + d];
            float f1 = Vb[(2 * p + 1) * DDIM + d];
            uint32_t hw = prmt_hi(__float_as_uint(f0), __float_as_uint(f1));
            uint32_t lw = pack_bf2(f1 - trunc_bf(f1), f0 - trunc_bf(f0));
            uint32_t o = swz(((uint32_t)d << 7) + ((uint32_t)p << 2));
            *(uint32_t*)(vs + o) = hw;
            *(uint32_t*)(vs + 16384 + o) = lw;
        }
    }
    __syncthreads();
    // linear coalesced copy-out: 32KB / 256 threads = 8 x 16B each
    #pragma unroll
    for (int i = 0; i < 8; i++) {
        int e = (i * 256 + tid) * 16;
        *(float4*)(out + SM_VHI + e) = *(const float4*)(vs + e);
    }
}

// ===========================================================================
// tcgen05 kernel — only real on the sm_103a pass
// ===========================================================================
#if !defined(__CUDA_ARCH__) || defined(__CUDA_ARCH_FEAT_SM103_ALL) || \
    (defined(__CUDA_ARCH_SPECIFIC__) && (__CUDA_ARCH_SPECIFIC__ >= 1000))
#define TC_PATH_COMPILED 1
#else
#define TC_PATH_COMPILED 0
#endif
#if defined(__CUDA_ARCH__) && TC_PATH_COMPILED
#define TC_DEV 1
#else
#define TC_DEV 0
#endif

#define T_QHI 0
#define T_QLO 64
#define T_S   128
#define T_PHI 192
#define T_PLO 224
#define T_O   256
#define TMEM_COLS 512

#define IDESC_N64  0x8100490u
#define IDESC_N128 0x8200490u

static constexpr uint64_t DESC_BASE =
    (uint64_t(2) << 61) | (uint64_t(1) << 46) | (uint64_t(64) << 32) | (uint64_t(1) << 16);
static __device__ __forceinline__ uint64_t mk_desc(uint32_t addr) {
    return DESC_BASE | ((uint64_t)(addr >> 4) & 0x3FFFull);
}

#if TC_DEV
static __device__ __forceinline__ void mma_f16(uint32_t d, uint32_t a, uint64_t bdesc,
                                               uint32_t idesc, int acc) {
    asm volatile(
        "{\n\t.reg .pred p;\n\tsetp.ne.u32 p,%5,0;\n\t"
        "tcgen05.mma.cta_group::1.kind::f16 [%0],[%1],%2,%3,{%4,%4,%4,%4},p;\n\t}"
        :: "r"(d), "r"(a), "l"(bdesc), "r"(idesc), "r"(0u), "r"((uint32_t)acc) : "memory");
}

#define TMEM_ALLOC(sa, n)  asm volatile("tcgen05.alloc.cta_group::1.sync.aligned.shared::cta.b32 [%0], %1;" :: "r"(sa), "r"((uint32_t)(n)) : "memory")
#define TMEM_DEALLOC(t, n) asm volatile("tcgen05.dealloc.cta_group::1.sync.aligned.b32 %0, %1;" :: "r"(t), "r"((uint32_t)(n)))
#define TMEM_RELINQ()      asm volatile("tcgen05.relinquish_alloc_permit.cta_group::1.sync.aligned;")
#define TC_COMMIT(mb)      asm volatile("tcgen05.commit.cta_group::1.mbarrier::arrive::one.shared::cluster.b64 [%0];" :: "r"(mb) : "memory")
#define TC_WAIT_LD()       asm volatile("tcgen05.wait::ld.sync.aligned;" ::: "memory")
#define TC_WAIT_ST()       asm volatile("tcgen05.wait::st.sync.aligned;" ::: "memory")
#define TC_FENCE_BEFORE()  asm volatile("tcgen05.fence::before_thread_sync;" ::: "memory")
#define TC_FENCE_AFTER()   asm volatile("tcgen05.fence::after_thread_sync;" ::: "memory")
#define MBAR_INIT(mb, c)   asm volatile("mbarrier.init.shared.b64 [%0], %1;" :: "r"(mb), "r"((uint32_t)(c)) : "memory")
#define CP_ASYNC16(dst, src) asm volatile("cp.async.cg.shared.global [%0], [%1], 16;" :: "r"(dst), "l"(src) : "memory")
#define CP_COMMIT()        asm volatile("cp.async.commit_group;" ::: "memory")
#define CP_WAIT0()         asm volatile("cp.async.wait_group 0;" ::: "memory")
#define FENCE_PROXY()      asm volatile("fence.proxy.async.shared::cta;" ::: "memory")

static __device__ __forceinline__ void mbar_wait(uint32_t mb, uint32_t parity) {
    asm volatile(
        "{\n\t.reg .pred P;\n\t"
        "W%=:\n\tmbarrier.try_wait.parity.acquire.cta.shared::cta.b64 P, [%0], %1, 0x989680;\n\t"
        "@P bra.uni D%=;\n\tbra.uni W%=;\n\tD%=:\n\t}"
        :: "r"(mb), "r"(parity) : "memory");
}

#define LDTM_X8(r, a) \
    asm volatile("tcgen05.ld.sync.aligned.32x32b.x8.b32 " \
        "{%0,%1,%2,%3,%4,%5,%6,%7}, [%8];" \
        : "=r"((r)[0]),"=r"((r)[1]),"=r"((r)[2]),"=r"((r)[3]),"=r"((r)[4]),"=r"((r)[5]),"=r"((r)[6]),"=r"((r)[7]) \
        : "r"(a))

#define LDTM_X16(r, a) \
    asm volatile("tcgen05.ld.sync.aligned.32x32b.x16.b32 " \
        "{%0,%1,%2,%3,%4,%5,%6,%7,%8,%9,%10,%11,%12,%13,%14,%15}, [%16];" \
        : "=r"((r)[0]),"=r"((r)[1]),"=r"((r)[2]),"=r"((r)[3]),"=r"((r)[4]),"=r"((r)[5]),"=r"((r)[6]),"=r"((r)[7]), \
          "=r"((r)[8]),"=r"((r)[9]),"=r"((r)[10]),"=r"((r)[11]),"=r"((r)[12]),"=r"((r)[13]),"=r"((r)[14]),"=r"((r)[15]) \
        : "r"(a))

#define STTM_X4(a, r) \
    asm volatile("tcgen05.st.sync.aligned.32x32b.x4.b32 [%0], {%1,%2,%3,%4};" \
        :: "r"(a), "r"((r)[0]),"r"((r)[1]),"r"((r)[2]),"r"((r)[3]) : "memory")

#define STTM_X16(a, r) \
    asm volatile("tcgen05.st.sync.aligned.32x32b.x16.b32 [%0], " \
        "{%1,%2,%3,%4,%5,%6,%7,%8,%9,%10,%11,%12,%13,%14,%15,%16};" \
        :: "r"(a), \
          "r"((r)[0]),"r"((r)[1]),"r"((r)[2]),"r"((r)[3]),"r"((r)[4]),"r"((r)[5]),"r"((r)[6]),"r"((r)[7]), \
          "r"((r)[8]),"r"((r)[9]),"r"((r)[10]),"r"((r)[11]),"r"((r)[12]),"r"((r)[13]),"r"((r)[14]),"r"((r)[15]) \
        : "memory")

// 64KB blob -> smem, threads 0-255, 16 x 16B each, coalesced
static __device__ __forceinline__ void copy_blob(uint32_t dst, const unsigned char* src, int t) {
    #pragma unroll
    for (int i = 0; i < 16; i++) {
        uint32_t off = (uint32_t)((i * 256 + t) * 16);
        CP_ASYNC16(dst + off, src + off);
    }
    CP_COMMIT();
}

static __device__ __forceinline__ void issue_g1(uint32_t tmem, uint32_t sb, int buf) {
    const int DOFF[8] = {0, 2, 4, 6, 512, 514, 516, 518};
    uint64_t dh = mk_desc(sb + buf * SM_BUFSZ + SM_KHI);
    uint64_t dl = mk_desc(sb + buf * SM_BUFSZ + SM_KLO);
    #pragma unroll
    for (int ks = 0; ks < 8; ks++)
        mma_f16(tmem + T_S, tmem + T_QHI + ks * 8, dh + DOFF[ks], IDESC_N64, ks != 0);
    #pragma unroll
    for (int ks = 0; ks < 8; ks++)
        mma_f16(tmem + T_S, tmem + T_QHI + ks * 8, dl + DOFF[ks], IDESC_N64, 1);
    #pragma unroll
    for (int ks = 0; ks < 8; ks++)
        mma_f16(tmem + T_S, tmem + T_QLO + ks * 8, dh + DOFF[ks], IDESC_N64, 1);
}

static __device__ __forceinline__ void issue_g2(uint32_t tmem, uint32_t sb, int buf, int first) {
    uint64_t dh = mk_desc(sb + buf * SM_BUFSZ + SM_VHI);
    uint64_t dl = mk_desc(sb + buf * SM_BUFSZ + SM_VLO);
    #pragma unroll
    for (int ks = 0; ks < 4; ks++)
        mma_f16(tmem + T_O, tmem + T_PHI + ks * 8, dh + ks * 2, IDESC_N128, !(first && ks == 0));
    #pragma unroll
    for (int ks = 0; ks < 4; ks++)
        mma_f16(tmem + T_O, tmem + T_PHI + ks * 8, dl + ks * 2, IDESC_N128, 1);
    #pragma unroll
    for (int ks = 0; ks < 4; ks++)
        mma_f16(tmem + T_O, tmem + T_PLO + ks * 8, dh + ks * 2, IDESC_N128, 1);
}
#endif  // TC_DEV

__global__ __launch_bounds__(1024, 1)
void attn_tc_kernel(const float* __restrict__ Qg, float* __restrict__ Og) {
#if TC_DEV
    extern __shared__ __align__(1024) char smem[];
    const uint32_t sb = smem_u32(smem);
    const int tid = threadIdx.x;
    const int w = tid >> 5, lane = tid & 31;
    const int sub = w & 3, oct = w >> 2;      // oct = column octet 0..7
    const int row = sub * 32 + lane;
    const int bh = blockIdx.y;
    const int q0 = blockIdx.x * BM;
    const float* Qp = Qg + ((size_t)bh * SS + q0) * DDIM;
    const unsigned char* blob = g_blob + ((size_t)(bh * NKB) << 16);

    if (w == 0) TMEM_ALLOC(sb + SM_TPTR, TMEM_COLS);
    if (tid == 0) { MBAR_INIT(sb + SM_MB1, 1); MBAR_INIT(sb + SM_MB2, 1); }
    __syncthreads();
    uint32_t tmem;
    asm volatile("ld.shared.b32 %0, [%1];" : "=r"(tmem) : "r"(sb + SM_TPTR));

    // ---- prologue: buf0 copy (threads 0-255) + Q -> TMEM (threads 0-127) ----
    if (tid < 256) copy_blob(sb + 0, blob, tid);
    if (tid < 128) {
        const float* qr = Qp + tid * DDIM;
        uint32_t woff = ((uint32_t)((tid >> 5) & 3)) << 21;
        #pragma unroll
        for (int hb = 0; hb < 4; hb++) {
            uint32_t hi[16], lo[16];
            #pragma unroll
            for (int c4 = 0; c4 < 8; c4++) {
                float4 u = *(const float4*)(qr + hb * 32 + c4 * 4);
                hi[2 * c4]     = prmt_hi(__float_as_uint(u.x), __float_as_uint(u.y));
                hi[2 * c4 + 1] = prmt_hi(__float_as_uint(u.z), __float_as_uint(u.w));
                lo[2 * c4]     = pack_bf2(u.y - trunc_bf(u.y), u.x - trunc_bf(u.x));
                lo[2 * c4 + 1] = pack_bf2(u.w - trunc_bf(u.w), u.z - trunc_bf(u.z));
            }
            STTM_X16(tmem + T_QHI + hb * 16 + woff, hi);
            STTM_X16(tmem + T_QLO + hb * 16 + woff, lo);
        }
        TC_WAIT_ST();
    }
    CP_WAIT0();
    FENCE_PROXY();
    TC_FENCE_BEFORE();
    __syncthreads();
    if (tid == 0) {
        TC_FENCE_AFTER();
        issue_g1(tmem, sb, 0);
        TC_COMMIT(sb + SM_MB1);
    }

    const float scale = 0.08838834764831845f;  // 1/sqrt(128)
    float dsum = 0.f;

    for (int kb = 0; kb < NKB; kb++) {
        // A: copy gang prefetches next KV blob (after GEMM2(kb-1) frees the buffer)
        if (tid < 256) {
            if (kb > 0) mbar_wait(sb + SM_MB2, (kb - 1) & 1);
            if (kb < NKB - 1)
                copy_blob(sb + (((kb + 1) & 1) ? SM_BUFSZ : 0),
                          blob + ((size_t)(kb + 1) << 16), tid);
        }
        // B: threefry mask bits (index-only; overlaps GEMM1(kb))
        uint32_t base = ((uint32_t)bh << 22) | ((uint32_t)(q0 + row) << 11)
                      | (uint32_t)(kb * BN + oct * 8);
        uint32_t mbits = 0;
        #pragma unroll
        for (int t = 0; t < 8; t++)
            mbits |= (tf_word(base + t) >> 31) << t;
        // C: S ready -> LDTM (each warp its 8-col octet)
        mbar_wait(sb + SM_MB1, kb & 1);
        TC_FENCE_AFTER();
        uint32_t sr[8];
        LDTM_X8(sr, tmem + T_S + oct * 8);
        TC_WAIT_LD();
        TC_FENCE_BEFORE();
        // D: copies done + visible to MMA; S tile free
        CP_WAIT0();
        FENCE_PROXY();
        __syncthreads();
        // E: launch next GEMM1 into freed S
        if (tid == 0 && kb < NKB - 1) {
            TC_FENCE_AFTER();
            issue_g1(tmem, sb, (kb + 1) & 1);
            TC_COMMIT(sb + SM_MB1);
        }
        // F: exp + mask + bf16 split -> P
        uint32_t phi[4], plo[4];
        #pragma unroll
        for (int t2 = 0; t2 < 4; t2++) {
            float e0 = __expf(__uint_as_float(sr[2 * t2]) * scale);
            float e1 = __expf(__uint_as_float(sr[2 * t2 + 1]) * scale);
            dsum += e0 + e1;
            float p0 = (mbits & (1u << (2 * t2)))     ? 0.f : e0;
            float p1 = (mbits & (1u << (2 * t2 + 1))) ? 0.f : e1;
            phi[t2] = prmt_hi(__float_as_uint(p0), __float_as_uint(p1));
            plo[t2] = pack_bf2(p1 - trunc_bf(p1), p0 - trunc_bf(p0));
        }
        uint32_t woff = ((uint32_t)sub) << 21;
        STTM_X4(tmem + T_PHI + oct * 4 + woff, phi);
        STTM_X4(tmem + T_PLO + oct * 4 + woff, plo);
        TC_WAIT_ST();
        TC_FENCE_BEFORE();
        __syncthreads();
        // G: launch GEMM2
        if (tid == 0) {
            TC_FENCE_AFTER();
            issue_g2(tmem, sb, kb & 1, kb == 0);
            TC_COMMIT(sb + SM_MB2);
        }
    }

    mbar_wait(sb + SM_MB2, (NKB - 1) & 1);
    TC_FENCE_AFTER();

    // denominator reduce across the 8 column octets
    ((float*)(smem + SM_DSUM))[row * 8 + oct] = dsum;
    __syncthreads();
    float tot = 0.f;
    #pragma unroll
    for (int i = 0; i < 8; i++)
        tot += ((float*)(smem + SM_DSUM))[row * 8 + i];
    float rs = 2.0f / tot;   // dropout 1/(1-p)=2 folded in

    uint32_t orv[16];
    LDTM_X16(orv, tmem + T_O + oct * 16);
    TC_WAIT_LD();
    TC_FENCE_BEFORE();
    size_t orow = ((size_t)bh * SS + (size_t)(q0 + row)) * DDIM;
    #pragma unroll
    for (int t = 0; t < 16; t++)
        Og[orow + oct * 16 + t] = __uint_as_float(orv[t]) * rs;

    __syncthreads();
    if (w == 0) { TMEM_RELINQ(); TMEM_DEALLOC(tmem, TMEM_COLS); }
#else
    (void)Qg; (void)Og;
#endif
}

// ===========================================================================
// host dispatch
// ===========================================================================
extern "C" void kernel_launch(void* const* d_in, const int* in_sizes, int n_in,
                              void* d_out, int out_size) {
    (void)in_sizes; (void)n_in; (void)out_size;
    const float* Q = (const float*)d_in[0];
    const float* K = (const float*)d_in[1];
    const float* V = (const float*)d_in[2];
    float* O = (float*)d_out;

    cudaFuncAttributes fa;
    bool tc_ok = (cudaFuncGetAttributes(&fa, attn_tc_kernel) == cudaSuccess)
               && fa.numRegs > 40;

    if (tc_ok) {
        prep_kv_kernel<<<1024, 256>>>(K, V);
        cudaFuncSetAttribute(attn_tc_kernel,
                             cudaFuncAttributeMaxDynamicSharedMemorySize, TC_SMEM);
        dim3 grid(SS / BM, 32);
        attn_tc_kernel<<<grid, 1024, TC_SMEM>>>(Q, O);
    } else {
        cudaFuncSetAttribute(attn_dropout_kernel,
                             cudaFuncAttributeMaxDynamicSharedMemorySize, FB_SMEM);
        dim3 grid(SS / FBM, 32);
        attn_dropout_kernel<<<grid, NT, FB_SMEM>>>(Q, K, V, O);
    }
}